// round 1
// baseline (speedup 1.0000x reference)
#include <cuda_runtime.h>

#define NN 50000
#define EE 600000
#define HH 128
#define LL 4
#define GG 256
#define CC 10
#define BNEPS 1e-5f

// ---------------- scratch (static device globals; no allocation) -------------
__device__ float g_h[(size_t)NN * HH];      // node features after layer i
__device__ float g_agg[(size_t)NN * HH];    // (1+eps)*h, then += neighbor sum
__device__ float g_z1[(size_t)NN * HH];     // output of Linear1 (pre-BN)
__device__ float g_z2[(size_t)NN * HH];     // output of Linear2 (pre-BN)
__device__ float g_pooled[GG * LL * HH];    // [G, L*H] pooled features
__device__ float g_stats[LL * 2 * 2 * HH];  // [layer][stage][sum|sumsq][H]

__device__ __forceinline__ void red_add_v4(float* p, float4 v) {
    asm volatile("red.global.add.v4.f32 [%0], {%1,%2,%3,%4};"
                 :: "l"(p), "f"(v.x), "f"(v.y), "f"(v.z), "f"(v.w) : "memory");
}

// ---------------- zero pooled + stats (per launch; graph-replay safe) --------
__global__ void zero_kernel() {
    const int tot = GG * LL * HH + LL * 2 * 2 * HH;
    for (int i = blockIdx.x * blockDim.x + threadIdx.x; i < tot;
         i += gridDim.x * blockDim.x) {
        if (i < GG * LL * HH) g_pooled[i] = 0.f;
        else                  g_stats[i - GG * LL * HH] = 0.f;
    }
}

// ---------------- layer-0 init: agg = (1+eps[0]) * x -------------------------
__global__ void init_kernel(const float* __restrict__ x,
                            const float* __restrict__ eps) {
    const float e = 1.f + eps[0];
    const float4* x4 = (const float4*)x;
    float4* a4 = (float4*)g_agg;
    const int tot = NN * HH / 4;
    for (int i = blockIdx.x * blockDim.x + threadIdx.x; i < tot;
         i += gridDim.x * blockDim.x) {
        float4 v = x4[i];
        v.x *= e; v.y *= e; v.z *= e; v.w *= e;
        a4[i] = v;
    }
}

// ---------------- edge scatter: agg[dst] += h[src] ---------------------------
// one warp per edge; lane l handles float4 l of the 128-float row
__global__ void edge_kernel(const float* __restrict__ x, int useX,
                            const int* __restrict__ ei) {
    const float* hsrc = useX ? x : g_h;
    const int lane = threadIdx.x & 31;
    int warp = (blockIdx.x * blockDim.x + threadIdx.x) >> 5;
    const int nw = (gridDim.x * blockDim.x) >> 5;
    for (int e = warp; e < EE; e += nw) {
        const int s = __ldg(ei + e);
        const int d = __ldg(ei + EE + e);
        float4 v = __ldg(((const float4*)(hsrc + (size_t)s * HH)) + lane);
        red_add_v4(g_agg + (size_t)d * HH + (lane << 2), v);
    }
}

// ---------------- GEMM: Z = op(A) @ W + bias; epilogue computes BN stats -----
// BNRELU=0: A = g_agg -> Z = g_z1, stats -> stage 0
// BNRELU=1: A = relu(BN(g_z1)) -> Z = g_z2, stats -> stage 1
template <int BNRELU>
__global__ void gemm_kernel(int layer,
                            const float* __restrict__ W,
                            const float* __restrict__ bias,
                            const float* __restrict__ gamma,
                            const float* __restrict__ beta) {
    __shared__ float  As[64 * 33];
    __shared__ float4 Bs[32 * 32];
    __shared__ float  scA[HH], shA[HH];

    const float* A = BNRELU ? g_z1 : g_agg;
    float*       Z = BNRELU ? g_z2 : g_z1;
    float* statsOut = g_stats + (layer * 2 + BNRELU) * 2 * HH;

    const int t = threadIdx.x;
    if (BNRELU) {
        const float* st = g_stats + (layer * 2) * 2 * HH;  // z1 stats
        if (t < HH) {
            float mu  = st[t] * (1.f / NN);
            float var = st[HH + t] * (1.f / NN) - mu * mu;
            float r   = rsqrtf(var + BNEPS);
            float sc  = r * gamma[t];
            scA[t] = sc;
            shA[t] = beta[t] - mu * sc;
        }
        __syncthreads();
    }

    const int m0 = blockIdx.x * 64;
    const int tx = t & 31, ty = t >> 5;   // tx: 4 cols @ tx*4, ty: 8 rows @ ty*8

    float4 acc[8];
#pragma unroll
    for (int i = 0; i < 8; i++) acc[i] = make_float4(0.f, 0.f, 0.f, 0.f);

    for (int k0 = 0; k0 < HH; k0 += 32) {
#pragma unroll
        for (int j = 0; j < 8; j++) {            // A tile 64x32
            int idx = t + j * 256;
            int r = idx >> 5, c = idx & 31;
            int m = m0 + r;
            float v = (m < NN) ? __ldg(A + (size_t)m * HH + k0 + c) : 0.f;
            if (BNRELU) v = fmaxf(fmaf(v, scA[k0 + c], shA[k0 + c]), 0.f);
            As[r * 33 + c] = v;
        }
#pragma unroll
        for (int j = 0; j < 4; j++) {            // B tile 32x128 (as float4)
            int idx = t + j * 256;
            int r = idx >> 5, c4 = idx & 31;
            Bs[r * 32 + c4] = __ldg(((const float4*)(W + (size_t)(k0 + r) * HH)) + c4);
        }
        __syncthreads();
#pragma unroll
        for (int k = 0; k < 32; k++) {
            float4 b = Bs[k * 32 + tx];
#pragma unroll
            for (int i = 0; i < 8; i++) {
                float a = As[(ty * 8 + i) * 33 + k];
                acc[i].x = fmaf(a, b.x, acc[i].x);
                acc[i].y = fmaf(a, b.y, acc[i].y);
                acc[i].z = fmaf(a, b.z, acc[i].z);
                acc[i].w = fmaf(a, b.w, acc[i].w);
            }
        }
        __syncthreads();
    }

    const float4 bb = __ldg(((const float4*)bias) + tx);
    float4 s  = make_float4(0.f, 0.f, 0.f, 0.f);
    float4 s2 = make_float4(0.f, 0.f, 0.f, 0.f);
#pragma unroll
    for (int i = 0; i < 8; i++) {
        int m = m0 + ty * 8 + i;
        if (m < NN) {
            float4 z;
            z.x = acc[i].x + bb.x; z.y = acc[i].y + bb.y;
            z.z = acc[i].z + bb.z; z.w = acc[i].w + bb.w;
            ((float4*)(Z + (size_t)m * HH))[tx] = z;
            s.x += z.x; s.y += z.y; s.z += z.z; s.w += z.w;
            s2.x = fmaf(z.x, z.x, s2.x); s2.y = fmaf(z.y, z.y, s2.y);
            s2.z = fmaf(z.z, z.z, s2.z); s2.w = fmaf(z.w, z.w, s2.w);
        }
    }
    const int c0 = tx * 4;
    atomicAdd(&statsOut[c0 + 0], s.x);
    atomicAdd(&statsOut[c0 + 1], s.y);
    atomicAdd(&statsOut[c0 + 2], s.z);
    atomicAdd(&statsOut[c0 + 3], s.w);
    atomicAdd(&statsOut[HH + c0 + 0], s2.x);
    atomicAdd(&statsOut[HH + c0 + 1], s2.y);
    atomicAdd(&statsOut[HH + c0 + 2], s2.z);
    atomicAdd(&statsOut[HH + c0 + 3], s2.w);
}

// ---------------- BN(z2)+ReLU -> h; pool into g_pooled; init next agg -------
__global__ void postbn_kernel(int layer,
                              const int* __restrict__ batch,
                              const float* __restrict__ eps,
                              const float* __restrict__ gamma,
                              const float* __restrict__ beta,
                              int lastLayer) {
    const int q = threadIdx.x & 31;      // float4 index within the 128-col row
    const int slot = threadIdx.x >> 5;   // 0..7 : node within block
    const float* st = g_stats + (layer * 2 + 1) * 2 * HH;

    float scv[4], shv[4];
#pragma unroll
    for (int j = 0; j < 4; j++) {
        int c = q * 4 + j;
        float mu  = st[c] * (1.f / NN);
        float var = st[HH + c] * (1.f / NN) - mu * mu;
        float r   = rsqrtf(var + BNEPS);
        scv[j] = r * gamma[c];
        shv[j] = beta[c] - mu * scv[j];
    }
    const float epn = lastLayer ? 0.f : (1.f + eps[layer + 1]);

    for (int n = blockIdx.x * 8 + slot; n < NN; n += gridDim.x * 8) {
        float4 z = ((const float4*)(g_z2 + (size_t)n * HH))[q];
        float4 h;
        h.x = fmaxf(fmaf(z.x, scv[0], shv[0]), 0.f);
        h.y = fmaxf(fmaf(z.y, scv[1], shv[1]), 0.f);
        h.z = fmaxf(fmaf(z.z, scv[2], shv[2]), 0.f);
        h.w = fmaxf(fmaf(z.w, scv[3], shv[3]), 0.f);
        if (!lastLayer) {
            ((float4*)(g_h + (size_t)n * HH))[q] = h;
            float4 a = make_float4(epn * h.x, epn * h.y, epn * h.z, epn * h.w);
            ((float4*)(g_agg + (size_t)n * HH))[q] = a;
        }
        int b = __ldg(batch + n);
        red_add_v4(g_pooled + b * (LL * HH) + layer * HH + q * 4, h);
    }
}

// ---------------- head: out = relu(pooled @ fc1 + b1) @ fc2 + b2 ------------
__global__ void head_kernel(const float* __restrict__ fc1w,
                            const float* __restrict__ fc1b,
                            const float* __restrict__ fc2w,
                            const float* __restrict__ fc2b,
                            float* __restrict__ out) {
    __shared__ float p[LL * HH];   // 512
    __shared__ float tbuf[HH];     // 128
    const int g = blockIdx.x;
    const int j = threadIdx.x;     // 0..127
    for (int k = j; k < LL * HH; k += HH) p[k] = g_pooled[g * (LL * HH) + k];
    __syncthreads();
    float acc = __ldg(fc1b + j);
#pragma unroll 4
    for (int k = 0; k < LL * HH; k++) acc = fmaf(p[k], __ldg(fc1w + k * HH + j), acc);
    tbuf[j] = fmaxf(acc, 0.f);
    __syncthreads();
    if (j < CC) {
        float o = __ldg(fc2b + j);
#pragma unroll 4
        for (int k = 0; k < HH; k++) o = fmaf(tbuf[k], __ldg(fc2w + k * CC + j), o);
        out[g * CC + j] = o;
    }
}

// ---------------- launch -----------------------------------------------------
extern "C" void kernel_launch(void* const* d_in, const int* in_sizes, int n_in,
                              void* d_out, int out_size) {
    const float* x    = (const float*)d_in[0];
    const int*   ei   = (const int*)  d_in[1];
    const int*   batch= (const int*)  d_in[2];
    const float* W1   = (const float*)d_in[3];
    const float* b1   = (const float*)d_in[4];
    const float* g1   = (const float*)d_in[5];
    const float* bt1  = (const float*)d_in[6];
    const float* W2   = (const float*)d_in[7];
    const float* b2   = (const float*)d_in[8];
    const float* g2   = (const float*)d_in[9];
    const float* bt2  = (const float*)d_in[10];
    const float* eps  = (const float*)d_in[11];
    const float* fc1w = (const float*)d_in[12];
    const float* fc1b = (const float*)d_in[13];
    const float* fc2w = (const float*)d_in[14];
    const float* fc2b = (const float*)d_in[15];
    float* out = (float*)d_out;

    zero_kernel<<<130, 256>>>();
    init_kernel<<<1024, 256>>>(x, eps);

    const int gemmBlocks = (NN + 63) / 64;  // 782
    for (int i = 0; i < LL; i++) {
        edge_kernel<<<2048, 256>>>(x, i == 0 ? 1 : 0, ei);
        gemm_kernel<0><<<gemmBlocks, 256>>>(i, W1 + i * HH * HH, b1 + i * HH,
                                            (const float*)0, (const float*)0);
        gemm_kernel<1><<<gemmBlocks, 256>>>(i, W2 + i * HH * HH, b2 + i * HH,
                                            g1 + i * HH, bt1 + i * HH);
        postbn_kernel<<<2048, 256>>>(i, batch, eps, g2 + i * HH, bt2 + i * HH,
                                     i == LL - 1 ? 1 : 0);
    }
    head_kernel<<<GG, HH>>>(fc1w, fc1b, fc2w, fc2b, out);
}

// round 4
// speedup vs baseline: 3.6250x; 3.6250x over previous
#include <cuda_runtime.h>

#define NN 50000
#define EE 600000
#define HH 128
#define LL 4
#define GG 256
#define CC 10
#define BNEPS 1e-5f

// ---------------- scratch (static device globals; no allocation) -------------
__device__ float g_h[(size_t)NN * HH];
__device__ float g_agg[(size_t)NN * HH];
__device__ float g_z1[(size_t)NN * HH];
__device__ float g_z2[(size_t)NN * HH];
__device__ float g_pooled[GG * LL * HH];
__device__ float g_stats[LL * 2 * 2 * HH];   // [layer][stage][sum|sumsq][H]
__device__ int   g_deg[NN];
__device__ int   g_rowptr[NN];
__device__ int   g_cursor[NN];
__device__ int   g_srclist[EE];

__device__ __forceinline__ void red_add_v4(float* p, float4 v) {
    asm volatile("red.global.add.v4.f32 [%0], {%1,%2,%3,%4};"
                 :: "l"(p), "f"(v.x), "f"(v.y), "f"(v.z), "f"(v.w) : "memory");
}

// ---------------- zero pooled + stats + degree -------------------------------
__global__ void zero_kernel() {
    const int P = GG * LL * HH;            // 131072
    const int S = LL * 2 * 2 * HH;         // 2048
    const int tot = P + S + NN;
    for (int i = blockIdx.x * blockDim.x + threadIdx.x; i < tot;
         i += gridDim.x * blockDim.x) {
        if (i < P) g_pooled[i] = 0.f;
        else if (i < P + S) g_stats[i - P] = 0.f;
        else g_deg[i - P - S] = 0;
    }
}

// ---------------- CSR build --------------------------------------------------
__global__ void count_kernel(const int* __restrict__ ei) {
    int e = blockIdx.x * blockDim.x + threadIdx.x;
    if (e < EE) atomicAdd(&g_deg[__ldg(ei + EE + e)], 1);
}

__global__ void scan_kernel() {
    __shared__ int ssum[1024];
    const int t = threadIdx.x;
    const int CH = (NN + 1023) / 1024;     // 49
    int start = t * CH;
    int end = start + CH; if (end > NN) end = NN;
    int s = 0;
    for (int i = start; i < end; i++) s += g_deg[i];
    ssum[t] = s;
    __syncthreads();
    for (int off = 1; off < 1024; off <<= 1) {
        int v = (t >= off) ? ssum[t - off] : 0;
        __syncthreads();
        ssum[t] += v;
        __syncthreads();
    }
    int run = (t == 0) ? 0 : ssum[t - 1];
    for (int i = start; i < end; i++) {
        g_rowptr[i] = run;
        g_cursor[i] = run;
        run += g_deg[i];
    }
}

__global__ void fill_kernel(const int* __restrict__ ei) {
    int e = blockIdx.x * blockDim.x + threadIdx.x;
    if (e < EE) {
        int d = __ldg(ei + EE + e);
        int pos = atomicAdd(&g_cursor[d], 1);
        g_srclist[pos] = __ldg(ei + e);
    }
}

// ---------------- aggregation: agg[n] = (1+eps)*h[n] + sum_{src->n} h[src] ---
__global__ void agg_kernel(const float* __restrict__ x, int useX,
                           const float* __restrict__ eps, int layer) {
    const float4* h4 = (const float4*)(useX ? x : g_h);
    float4* a4 = (float4*)g_agg;
    const int lane = threadIdx.x & 31;
    int warp = (blockIdx.x * blockDim.x + threadIdx.x) >> 5;
    const int nw = (gridDim.x * blockDim.x) >> 5;
    const float e1 = 1.f + __ldg(eps + layer);
    for (int n = warp; n < NN; n += nw) {
        const int base = g_rowptr[n];
        const int deg = g_deg[n];
        float4 acc = h4[(size_t)n * 32 + lane];
        acc.x *= e1; acc.y *= e1; acc.z *= e1; acc.w *= e1;
        int i = 0;
        for (; i + 4 <= deg; i += 4) {
            int s0 = __ldg(g_srclist + base + i);
            int s1 = __ldg(g_srclist + base + i + 1);
            int s2 = __ldg(g_srclist + base + i + 2);
            int s3 = __ldg(g_srclist + base + i + 3);
            float4 v0 = h4[(size_t)s0 * 32 + lane];
            float4 v1 = h4[(size_t)s1 * 32 + lane];
            float4 v2 = h4[(size_t)s2 * 32 + lane];
            float4 v3 = h4[(size_t)s3 * 32 + lane];
            acc.x += v0.x + v1.x + v2.x + v3.x;
            acc.y += v0.y + v1.y + v2.y + v3.y;
            acc.z += v0.z + v1.z + v2.z + v3.z;
            acc.w += v0.w + v1.w + v2.w + v3.w;
        }
        for (; i < deg; i++) {
            int s = __ldg(g_srclist + base + i);
            float4 v = h4[(size_t)s * 32 + lane];
            acc.x += v.x; acc.y += v.y; acc.z += v.z; acc.w += v.w;
        }
        a4[(size_t)n * 32 + lane] = acc;
    }
}

// ---------------- GEMM: Z = op(A) @ W + bias; epilogue: BN stats -------------
// BNRELU=0: A = g_agg -> Z = g_z1, stats stage 0
// BNRELU=1: A = relu(BN(g_z1)) -> Z = g_z2, stats stage 1
template <int BNRELU>
__global__ __launch_bounds__(256, 2) void gemm_kernel(
        int layer,
        const float* __restrict__ W,
        const float* __restrict__ bias,
        const float* __restrict__ gamma,
        const float* __restrict__ beta) {
    __shared__ float  As[16][132];   // transposed A tile [k][m]
    __shared__ float4 Bs[16][32];    // B tile [k][c4]
    __shared__ float  red[16][128];  // stats reduction
    __shared__ float  scA[HH], shA[HH];

    const float* A = BNRELU ? g_z1 : g_agg;
    float*       Z = BNRELU ? g_z2 : g_z1;
    float* statsOut = g_stats + (layer * 2 + BNRELU) * 2 * HH;

    const int t = threadIdx.x;
    if (BNRELU) {
        const float* st = g_stats + (layer * 2) * 2 * HH;
        if (t < HH) {
            float mu  = st[t] * (1.f / NN);
            float var = st[HH + t] * (1.f / NN) - mu * mu;
            float r   = rsqrtf(var + BNEPS);
            float sc  = r * __ldg(gamma + t);
            scA[t] = sc;
            shA[t] = __ldg(beta + t) - mu * sc;
        }
        __syncthreads();
    }

    const int m0 = blockIdx.x * 128;
    const int tx = t & 15;          // col group: cols tx*4 and tx*4+64
    const int ty = t >> 4;          // row group: rows ty*4 and ty*4+64

    const float4* A4 = (const float4*)A;
    const float4* W4 = (const float4*)W;

    float4 accA[8], accB[8];
#pragma unroll
    for (int i = 0; i < 8; i++) {
        accA[i] = make_float4(0.f, 0.f, 0.f, 0.f);
        accB[i] = make_float4(0.f, 0.f, 0.f, 0.f);
    }

    for (int k0 = 0; k0 < HH; k0 += 16) {
        // A tile: 128 rows x 16 cols, stored transposed
#pragma unroll
        for (int j = 0; j < 2; j++) {
            int idx = t + j * 256;
            int row = idx >> 2, cq = idx & 3;
            int m = m0 + row;
            float4 v = make_float4(0.f, 0.f, 0.f, 0.f);
            if (m < NN) {
                v = A4[(size_t)m * 32 + (k0 >> 2) + cq];
                if (BNRELU) {
                    int c = k0 + cq * 4;
                    v.x = fmaxf(fmaf(v.x, scA[c + 0], shA[c + 0]), 0.f);
                    v.y = fmaxf(fmaf(v.y, scA[c + 1], shA[c + 1]), 0.f);
                    v.z = fmaxf(fmaf(v.z, scA[c + 2], shA[c + 2]), 0.f);
                    v.w = fmaxf(fmaf(v.w, scA[c + 3], shA[c + 3]), 0.f);
                }
            }
            As[cq * 4 + 0][row] = v.x;
            As[cq * 4 + 1][row] = v.y;
            As[cq * 4 + 2][row] = v.z;
            As[cq * 4 + 3][row] = v.w;
        }
        // B tile: 16 rows x 128 cols
#pragma unroll
        for (int j = 0; j < 2; j++) {
            int idx = t + j * 256;
            int kr = idx >> 5, c4 = idx & 31;
            Bs[kr][c4] = W4[(size_t)(k0 + kr) * 32 + c4];
        }
        __syncthreads();
#pragma unroll
        for (int k = 0; k < 16; k++) {
            float4 a0 = *(const float4*)&As[k][ty * 4];
            float4 a1 = *(const float4*)&As[k][ty * 4 + 64];
            float4 b0 = Bs[k][tx];
            float4 b1 = Bs[k][tx + 16];
            float ar[8] = {a0.x, a0.y, a0.z, a0.w, a1.x, a1.y, a1.z, a1.w};
#pragma unroll
            for (int r = 0; r < 8; r++) {
                accA[r].x = fmaf(ar[r], b0.x, accA[r].x);
                accA[r].y = fmaf(ar[r], b0.y, accA[r].y);
                accA[r].z = fmaf(ar[r], b0.z, accA[r].z);
                accA[r].w = fmaf(ar[r], b0.w, accA[r].w);
                accB[r].x = fmaf(ar[r], b1.x, accB[r].x);
                accB[r].y = fmaf(ar[r], b1.y, accB[r].y);
                accB[r].z = fmaf(ar[r], b1.z, accB[r].z);
                accB[r].w = fmaf(ar[r], b1.w, accB[r].w);
            }
        }
        __syncthreads();
    }

    // epilogue: bias, store, per-thread column sums
    const float4 bb0 = __ldg(((const float4*)bias) + tx);
    const float4 bb1 = __ldg(((const float4*)bias) + tx + 16);
    float4 s0 = make_float4(0.f, 0.f, 0.f, 0.f), s1 = s0, q0 = s0, q1 = s0;
    float4* Z4 = (float4*)Z;
#pragma unroll
    for (int r = 0; r < 8; r++) {
        int m = m0 + ty * 4 + ((r < 4) ? r : 64 + (r - 4));
        if (m < NN) {
            float4 z0, z1;
            z0.x = accA[r].x + bb0.x; z0.y = accA[r].y + bb0.y;
            z0.z = accA[r].z + bb0.z; z0.w = accA[r].w + bb0.w;
            z1.x = accB[r].x + bb1.x; z1.y = accB[r].y + bb1.y;
            z1.z = accB[r].z + bb1.z; z1.w = accB[r].w + bb1.w;
            Z4[(size_t)m * 32 + tx] = z0;
            Z4[(size_t)m * 32 + tx + 16] = z1;
            s0.x += z0.x; s0.y += z0.y; s0.z += z0.z; s0.w += z0.w;
            s1.x += z1.x; s1.y += z1.y; s1.z += z1.z; s1.w += z1.w;
            q0.x = fmaf(z0.x, z0.x, q0.x); q0.y = fmaf(z0.y, z0.y, q0.y);
            q0.z = fmaf(z0.z, z0.z, q0.z); q0.w = fmaf(z0.w, z0.w, q0.w);
            q1.x = fmaf(z1.x, z1.x, q1.x); q1.y = fmaf(z1.y, z1.y, q1.y);
            q1.z = fmaf(z1.z, z1.z, q1.z); q1.w = fmaf(z1.w, z1.w, q1.w);
        }
    }
    // block-reduce stats in smem -> 256 atomics per block
    *(float4*)&red[ty][tx * 4]      = s0;
    *(float4*)&red[ty][tx * 4 + 64] = s1;
    __syncthreads();
    if (t < 128) {
        float v = 0.f;
#pragma unroll
        for (int j = 0; j < 16; j++) v += red[j][t];
        atomicAdd(statsOut + t, v);
    }
    __syncthreads();
    *(float4*)&red[ty][tx * 4]      = q0;
    *(float4*)&red[ty][tx * 4 + 64] = q1;
    __syncthreads();
    if (t < 128) {
        float v = 0.f;
#pragma unroll
        for (int j = 0; j < 16; j++) v += red[j][t];
        atomicAdd(statsOut + HH + t, v);
    }
}

// ---------------- BN(z2)+ReLU -> h; pool into g_pooled ----------------------
__global__ void postbn_kernel(int layer,
                              const int* __restrict__ batch,
                              const float* __restrict__ gamma,
                              const float* __restrict__ beta,
                              int lastLayer) {
    const int q = threadIdx.x & 31;
    const int slot = threadIdx.x >> 5;
    const float* st = g_stats + (layer * 2 + 1) * 2 * HH;

    float scv[4], shv[4];
#pragma unroll
    for (int j = 0; j < 4; j++) {
        int c = q * 4 + j;
        float mu  = st[c] * (1.f / NN);
        float var = st[HH + c] * (1.f / NN) - mu * mu;
        float r   = rsqrtf(var + BNEPS);
        scv[j] = r * __ldg(gamma + c);
        shv[j] = __ldg(beta + c) - mu * scv[j];
    }

    for (int n = blockIdx.x * 8 + slot; n < NN; n += gridDim.x * 8) {
        float4 z = ((const float4*)(g_z2 + (size_t)n * HH))[q];
        float4 h;
        h.x = fmaxf(fmaf(z.x, scv[0], shv[0]), 0.f);
        h.y = fmaxf(fmaf(z.y, scv[1], shv[1]), 0.f);
        h.z = fmaxf(fmaf(z.z, scv[2], shv[2]), 0.f);
        h.w = fmaxf(fmaf(z.w, scv[3], shv[3]), 0.f);
        if (!lastLayer) ((float4*)(g_h + (size_t)n * HH))[q] = h;
        int b = __ldg(batch + n);
        red_add_v4(g_pooled + b * (LL * HH) + layer * HH + q * 4, h);
    }
}

// ---------------- head -------------------------------------------------------
__global__ void head_kernel(const float* __restrict__ fc1w,
                            const float* __restrict__ fc1b,
                            const float* __restrict__ fc2w,
                            const float* __restrict__ fc2b,
                            float* __restrict__ out) {
    __shared__ float p[LL * HH];
    __shared__ float tbuf[HH];
    const int g = blockIdx.x;
    const int j = threadIdx.x;
    for (int k = j; k < LL * HH; k += HH) p[k] = g_pooled[g * (LL * HH) + k];
    __syncthreads();
    float acc = __ldg(fc1b + j);
#pragma unroll 4
    for (int k = 0; k < LL * HH; k++) acc = fmaf(p[k], __ldg(fc1w + k * HH + j), acc);
    tbuf[j] = fmaxf(acc, 0.f);
    __syncthreads();
    if (j < CC) {
        float o = __ldg(fc2b + j);
#pragma unroll 4
        for (int k = 0; k < HH; k++) o = fmaf(tbuf[k], __ldg(fc2w + k * CC + j), o);
        out[g * CC + j] = o;
    }
}

// ---------------- launch -----------------------------------------------------
extern "C" void kernel_launch(void* const* d_in, const int* in_sizes, int n_in,
                              void* d_out, int out_size) {
    const float* x    = (const float*)d_in[0];
    const int*   ei   = (const int*)  d_in[1];
    const int*   batch= (const int*)  d_in[2];
    const float* W1   = (const float*)d_in[3];
    const float* b1   = (const float*)d_in[4];
    const float* g1   = (const float*)d_in[5];
    const float* bt1  = (const float*)d_in[6];
    const float* W2   = (const float*)d_in[7];
    const float* b2   = (const float*)d_in[8];
    const float* g2   = (const float*)d_in[9];
    const float* bt2  = (const float*)d_in[10];
    const float* eps  = (const float*)d_in[11];
    const float* fc1w = (const float*)d_in[12];
    const float* fc1b = (const float*)d_in[13];
    const float* fc2w = (const float*)d_in[14];
    const float* fc2b = (const float*)d_in[15];
    float* out = (float*)d_out;

    zero_kernel<<<180, 1024>>>();
    count_kernel<<<(EE + 255) / 256, 256>>>(ei);
    scan_kernel<<<1, 1024>>>();
    fill_kernel<<<(EE + 255) / 256, 256>>>(ei);

    const int gemmBlocks = (NN + 127) / 128;  // 391
    for (int i = 0; i < LL; i++) {
        agg_kernel<<<2048, 256>>>(x, i == 0 ? 1 : 0, eps, i);
        gemm_kernel<0><<<gemmBlocks, 256>>>(i, W1 + i * HH * HH, b1 + i * HH,
                                            (const float*)0, (const float*)0);
        gemm_kernel<1><<<gemmBlocks, 256>>>(i, W2 + i * HH * HH, b2 + i * HH,
                                            g1 + i * HH, bt1 + i * HH);
        postbn_kernel<<<2048, 256>>>(i, batch, g2 + i * HH, bt2 + i * HH,
                                     i == LL - 1 ? 1 : 0);
    }
    head_kernel<<<GG, HH>>>(fc1w, fc1b, fc2w, fc2b, out);
}